// round 2
// baseline (speedup 1.0000x reference)
#include <cuda_runtime.h>
#include <math.h>

#define S_LEN 8192
#define H_DIM 1024
#define N_OUT 3072
#define NHEAD 8
#define HDIM  128

// Scratch (allocation-free per the rules): Q/K/V in [head][s][d] layout.
__device__ float g_Q[NHEAD * S_LEN * HDIM];
__device__ float g_K[NHEAD * S_LEN * HDIM];
__device__ float g_V[NHEAD * S_LEN * HDIM];

// ---------------------------------------------------------------------------
// Kernel A: QKV = X @ W^T + bias, scattered into g_Q/g_K/g_V ([head][s][d]).
// X: [8192][1024] row-major, W: [3072][1024] row-major (both K-contiguous).
// 64x64 block tile, K-step 32, 256 threads, 4x4 micro-tile.
// ---------------------------------------------------------------------------
__global__ __launch_bounds__(256) void qkv_gemm_kernel(
    const float* __restrict__ X, const float* __restrict__ W,
    const float* __restrict__ bias)
{
    __shared__ __align__(16) float sA[32][68];  // sA[k][m] (transposed)
    __shared__ __align__(16) float sB[32][68];  // sB[k][n]

    const int m0 = blockIdx.y * 64;
    const int n0 = blockIdx.x * 64;
    const int tid = threadIdx.x;
    const int tx = tid & 15, ty = tid >> 4;

    float acc[4][4] = {};

    for (int k0 = 0; k0 < H_DIM; k0 += 32) {
        // Load 64x32 tiles of A and B (512 float4 each; 2 per thread per operand)
        #pragma unroll
        for (int r = 0; r < 2; r++) {
            int f = tid + r * 256;
            int row = f >> 3, c4 = f & 7;
            float4 a = *(const float4*)(X + (size_t)(m0 + row) * H_DIM + k0 + c4 * 4);
            sA[c4*4+0][row] = a.x; sA[c4*4+1][row] = a.y;
            sA[c4*4+2][row] = a.z; sA[c4*4+3][row] = a.w;
            float4 b = *(const float4*)(W + (size_t)(n0 + row) * H_DIM + k0 + c4 * 4);
            sB[c4*4+0][row] = b.x; sB[c4*4+1][row] = b.y;
            sB[c4*4+2][row] = b.z; sB[c4*4+3][row] = b.w;
        }
        __syncthreads();
        #pragma unroll 8
        for (int kk = 0; kk < 32; kk++) {
            float4 av = *(const float4*)(&sA[kk][ty * 4]);
            float4 bv = *(const float4*)(&sB[kk][tx * 4]);
            float a[4] = {av.x, av.y, av.z, av.w};
            float b[4] = {bv.x, bv.y, bv.z, bv.w};
            #pragma unroll
            for (int i = 0; i < 4; i++)
                #pragma unroll
                for (int j = 0; j < 4; j++)
                    acc[i][j] = fmaf(a[i], b[j], acc[i][j]);
        }
        __syncthreads();
    }

    // Epilogue: bias + scatter to [head][s][d]. 4 consecutive n stay inside
    // one (type, head) since tiles are 64-aligned and head_dim = 128.
    const int n_base = n0 + tx * 4;
    const int type = n_base >> 10;           // 0:Q 1:K 2:V
    const int head = (n_base & 1023) >> 7;
    const int d = n_base & 127;
    float* dst = (type == 0) ? g_Q : (type == 1) ? g_K : g_V;
    float4 bs = *(const float4*)(bias + n_base);
    #pragma unroll
    for (int i = 0; i < 4; i++) {
        int m = m0 + ty * 4 + i;
        float4 o;
        o.x = acc[i][0] + bs.x; o.y = acc[i][1] + bs.y;
        o.z = acc[i][2] + bs.z; o.w = acc[i][3] + bs.w;
        *(float4*)(dst + ((size_t)head * S_LEN + m) * HDIM + d) = o;
    }
}

// ---------------------------------------------------------------------------
// Kernel B: RoPE on Q and K (in place); softmax scale folded into Q.
// grid = S_LEN blocks, 512 threads: head = tid>>6, d = tid&63 (pair d, d+64)
// ---------------------------------------------------------------------------
__global__ __launch_bounds__(512) void rope_kernel(
    const float* __restrict__ cosp, const float* __restrict__ sinp)
{
    const int s = blockIdx.x;
    const int tid = threadIdx.x;
    const int head = tid >> 6;
    const int d = tid & 63;
    const float SCALE = 0.08838834764831845f;  // 128^-0.5

    float c1 = cosp[s * HDIM + d],      s1 = sinp[s * HDIM + d];
    float c2 = cosp[s * HDIM + d + 64], s2 = sinp[s * HDIM + d + 64];

    size_t base = ((size_t)head * S_LEN + s) * HDIM;

    float q1 = g_Q[base + d], q2 = g_Q[base + d + 64];
    g_Q[base + d]      = (q1 * c1 - q2 * s1) * SCALE;
    g_Q[base + d + 64] = (q2 * c2 + q1 * s2) * SCALE;

    float k1 = g_K[base + d], k2 = g_K[base + d + 64];
    g_K[base + d]      = k1 * c1 - k2 * s1;
    g_K[base + d + 64] = k2 * c2 + k1 * s2;
}

// ---------------------------------------------------------------------------
// Kernel C: causal flash attention, fp32.
// grid = (128 q-blocks [reversed for load balance], 8 heads), 256 threads.
// BLOCK_M = BLOCK_N = 64. Q/K staged transposed ([d][row]) for conflict-free
// float4 LDS; P staged via smem for the PV matmul. Online softmax.
// smem = 120832 B (dynamic).
// ---------------------------------------------------------------------------
__global__ __launch_bounds__(256) void attn_kernel(float* __restrict__ out)
{
    extern __shared__ float sm[];
    float* sQ = sm;               // [128][68]  sQ[k][m]
    float* sK = sQ + 128 * 68;    // [128][68]  sK[k][n]
    float* sV = sK + 128 * 68;    // [64][132]  sV[n][d]
    float* sP = sV + 64 * 132;    // [64][68]   sP[n][m]

    const int head = blockIdx.y;
    const int mb = (int)gridDim.x - 1 - (int)blockIdx.x;  // heavy blocks first
    const int q0 = mb * 64;
    const int tid = threadIdx.x;
    const int tx = tid & 15, ty = tid >> 4;

    const float* Qh = g_Q + (size_t)head * S_LEN * HDIM;
    const float* Kh = g_K + (size_t)head * S_LEN * HDIM;
    const float* Vh = g_V + (size_t)head * S_LEN * HDIM;

    // Load Q tile transposed (once per CTA)
    for (int f = tid; f < 2048; f += 256) {
        int row = f >> 5, c4 = f & 31;
        float4 v = *(const float4*)(Qh + (size_t)(q0 + row) * HDIM + c4 * 4);
        sQ[(c4*4+0)*68 + row] = v.x;
        sQ[(c4*4+1)*68 + row] = v.y;
        sQ[(c4*4+2)*68 + row] = v.z;
        sQ[(c4*4+3)*68 + row] = v.w;
    }

    float m_i[4], l_i[4], acc[4][8];
    #pragma unroll
    for (int i = 0; i < 4; i++) {
        m_i[i] = -INFINITY; l_i[i] = 0.f;
        #pragma unroll
        for (int j = 0; j < 8; j++) acc[i][j] = 0.f;
    }

    for (int nb = 0; nb <= mb; nb++) {
        const int k0 = nb * 64;

        // Load K (transposed) and V (natural) tiles
        for (int f = tid; f < 2048; f += 256) {
            int row = f >> 5, c4 = f & 31;
            float4 v = *(const float4*)(Kh + (size_t)(k0 + row) * HDIM + c4 * 4);
            sK[(c4*4+0)*68 + row] = v.x;
            sK[(c4*4+1)*68 + row] = v.y;
            sK[(c4*4+2)*68 + row] = v.z;
            sK[(c4*4+3)*68 + row] = v.w;
            float4 w = *(const float4*)(Vh + (size_t)(k0 + row) * HDIM + c4 * 4);
            *(float4*)(sV + row * 132 + c4 * 4) = w;
        }
        __syncthreads();

        // S = Q K^T  (scale already folded into Q)
        float sv[4][4] = {};
        #pragma unroll 8
        for (int k = 0; k < 128; k++) {
            float4 qv = *(const float4*)(sQ + k * 68 + ty * 4);
            float4 kv = *(const float4*)(sK + k * 68 + tx * 4);
            float a[4] = {qv.x, qv.y, qv.z, qv.w};
            float b[4] = {kv.x, kv.y, kv.z, kv.w};
            #pragma unroll
            for (int i = 0; i < 4; i++)
                #pragma unroll
                for (int j = 0; j < 4; j++)
                    sv[i][j] = fmaf(a[i], b[j], sv[i][j]);
        }

        // Causal mask on the diagonal block only
        if (nb == mb) {
            #pragma unroll
            for (int i = 0; i < 4; i++)
                #pragma unroll
                for (int j = 0; j < 4; j++)
                    if (k0 + tx * 4 + j > q0 + ty * 4 + i) sv[i][j] = -1e30f;
        }

        // Online softmax update (row stats shared by the 16 tx threads)
        float alpha[4];
        #pragma unroll
        for (int i = 0; i < 4; i++) {
            float mx = fmaxf(fmaxf(sv[i][0], sv[i][1]), fmaxf(sv[i][2], sv[i][3]));
            #pragma unroll
            for (int off = 8; off > 0; off >>= 1)
                mx = fmaxf(mx, __shfl_xor_sync(0xffffffffu, mx, off));
            float m_new = fmaxf(m_i[i], mx);
            alpha[i] = __expf(m_i[i] - m_new);   // exp(-inf)=0 on first block
            m_i[i] = m_new;

            float rs = 0.f;
            #pragma unroll
            for (int j = 0; j < 4; j++) {
                float p = __expf(sv[i][j] - m_new);
                sv[i][j] = p;
                rs += p;
            }
            #pragma unroll
            for (int off = 8; off > 0; off >>= 1)
                rs += __shfl_xor_sync(0xffffffffu, rs, off);
            l_i[i] = l_i[i] * alpha[i] + rs;
            #pragma unroll
            for (int j = 0; j < 8; j++) acc[i][j] *= alpha[i];
        }

        // Stage P transposed for the PV matmul
        #pragma unroll
        for (int i = 0; i < 4; i++)
            #pragma unroll
            for (int j = 0; j < 4; j++)
                sP[(tx * 4 + j) * 68 + ty * 4 + i] = sv[i][j];
        __syncthreads();

        // O += P @ V
        #pragma unroll 2
        for (int n = 0; n < 64; n++) {
            float4 pv = *(const float4*)(sP + n * 68 + ty * 4);
            float4 v0 = *(const float4*)(sV + n * 132 + tx * 8);
            float4 v1 = *(const float4*)(sV + n * 132 + tx * 8 + 4);
            float p[4] = {pv.x, pv.y, pv.z, pv.w};
            float vr[8] = {v0.x, v0.y, v0.z, v0.w, v1.x, v1.y, v1.z, v1.w};
            #pragma unroll
            for (int i = 0; i < 4; i++)
                #pragma unroll
                for (int j = 0; j < 8; j++)
                    acc[i][j] = fmaf(p[i], vr[j], acc[i][j]);
        }
        __syncthreads();
    }

    // Epilogue: normalize and write out[s][head][d] (row stride 1024)
    #pragma unroll
    for (int i = 0; i < 4; i++) {
        float inv = 1.0f / l_i[i];
        size_t base = (size_t)(q0 + ty * 4 + i) * (NHEAD * HDIM) + head * HDIM + tx * 8;
        float4 o0, o1;
        o0.x = acc[i][0] * inv; o0.y = acc[i][1] * inv;
        o0.z = acc[i][2] * inv; o0.w = acc[i][3] * inv;
        o1.x = acc[i][4] * inv; o1.y = acc[i][5] * inv;
        o1.z = acc[i][6] * inv; o1.w = acc[i][7] * inv;
        *(float4*)(out + base) = o0;
        *(float4*)(out + base + 4) = o1;
    }
}

// ---------------------------------------------------------------------------
extern "C" void kernel_launch(void* const* d_in, const int* in_sizes, int n_in,
                              void* d_out, int out_size)
{
    const float* x  = (const float*)d_in[0];  // layernorm_output [8192][1][1024]
    const float* fc = (const float*)d_in[1];  // freqs_cos [8192][1][1][128]
    const float* fs = (const float*)d_in[2];  // freqs_sin
    const float* w  = (const float*)d_in[3];  // qkv_weight [3072][1024]
    const float* b  = (const float*)d_in[4];  // qkv_bias [3072]
    float* out = (float*)d_out;               // [1][8192][8][128] fp32

    qkv_gemm_kernel<<<dim3(N_OUT / 64, S_LEN / 64), 256>>>(x, w, b);
    rope_kernel<<<S_LEN, 512>>>(fc, fs);

    const size_t attn_smem = (size_t)(2 * 128 * 68 + 64 * 132 + 64 * 68) * sizeof(float);
    cudaFuncSetAttribute(attn_kernel, cudaFuncAttributeMaxDynamicSharedMemorySize,
                         (int)attn_smem);
    attn_kernel<<<dim3(S_LEN / 64, NHEAD), 256, attn_smem>>>(out);
}

// round 3
// speedup vs baseline: 5.6403x; 5.6403x over previous
#include <cuda_runtime.h>
#include <cuda_fp16.h>
#include <math.h>

#define S_LEN 8192
#define H_IN  1024
#define NHEAD 8
#define HD    128
#define NEG   -1e30f

// Scratch device globals (allocation-free rule).
__device__ float  g_Q [NHEAD * S_LEN * HD];   // fp32 pre-rope
__device__ float  g_K [NHEAD * S_LEN * HD];
__device__ float  g_Qp[NHEAD * S_LEN * HD];   // tf32, k pair-permuted, scaled
__device__ float  g_Kp[NHEAD * S_LEN * HD];   // tf32, k pair-permuted
__device__ __half g_Vh[NHEAD * HD * S_LEN];   // fp16, [head][d][s]

__device__ __forceinline__ float rna_tf32(float x) {
    unsigned u; asm("cvt.rna.tf32.f32 %0, %1;" : "=r"(u) : "f"(x));
    return __uint_as_float(u);
}
__device__ __forceinline__ void mma_tf32(float* d,
    unsigned a0, unsigned a1, unsigned a2, unsigned a3, unsigned b0, unsigned b1)
{
    asm volatile(
        "mma.sync.aligned.m16n8k8.row.col.f32.tf32.tf32.f32 "
        "{%0,%1,%2,%3},{%4,%5,%6,%7},{%8,%9},{%0,%1,%2,%3};"
        : "+f"(d[0]), "+f"(d[1]), "+f"(d[2]), "+f"(d[3])
        : "r"(a0), "r"(a1), "r"(a2), "r"(a3), "r"(b0), "r"(b1));
}
__device__ __forceinline__ void mma_f16(float* d,
    unsigned a0, unsigned a1, unsigned a2, unsigned a3, unsigned b0, unsigned b1)
{
    asm volatile(
        "mma.sync.aligned.m16n8k16.row.col.f32.f16.f16.f32 "
        "{%0,%1,%2,%3},{%4,%5,%6,%7},{%8,%9},{%0,%1,%2,%3};"
        : "+f"(d[0]), "+f"(d[1]), "+f"(d[2]), "+f"(d[3])
        : "r"(a0), "r"(a1), "r"(a2), "r"(a3), "r"(b0), "r"(b1));
}
__device__ __forceinline__ void cpa16(unsigned dst, const void* src) {
    asm volatile("cp.async.cg.shared.global [%0], [%1], 16;" :: "r"(dst), "l"(src));
}
#define CP_COMMIT asm volatile("cp.async.commit_group;")
#define CP_WAIT0  asm volatile("cp.async.wait_group 0;" ::: "memory")

// pair permutation within 8-groups: logical (t, t+4) -> phys (2t, 2t+1)
__device__ __forceinline__ int ph8(int j) { return ((j & 3) << 1) | (j >> 2); }

// ---------------------------------------------------------------------------
// Kernel A: QKV GEMM, tf32 mma. BM=BN=128, BK=32, 256 thr (8 warps = 4m x 2n).
// smem: double-buffered X/W tiles, row stride 40 floats (conflict-free frags).
// ---------------------------------------------------------------------------
__global__ __launch_bounds__(256) void qkv_gemm_tf32(
    const float* __restrict__ X, const float* __restrict__ W,
    const float* __restrict__ bias)
{
    extern __shared__ float gsm[];
    float* sX = gsm;           // 2 x 128*40
    float* sW = gsm + 10240;   // 2 x 128*40

    const int tid = threadIdx.x, lane = tid & 31, w = tid >> 5;
    const int g = lane >> 2, tg = lane & 3;
    const int wm = w & 3, wn = w >> 2;
    const int m0 = blockIdx.y * 128, n0 = blockIdx.x * 128;

    float c[2][8][4];
    #pragma unroll
    for (int i = 0; i < 2; i++)
        #pragma unroll
        for (int j = 0; j < 8; j++)
            #pragma unroll
            for (int q = 0; q < 4; q++) c[i][j][q] = 0.f;

    float4 rx[4], rw[4];
    auto LDG = [&](int k0) {
        #pragma unroll
        for (int i = 0; i < 4; i++) {
            int id = tid + i * 256, row = id >> 3, c4 = id & 7;
            rx[i] = *(const float4*)(X + (size_t)(m0 + row) * H_IN + k0 + c4 * 4);
            rw[i] = *(const float4*)(W + (size_t)(n0 + row) * H_IN + k0 + c4 * 4);
        }
    };
    auto STS = [&](int b) {
        #pragma unroll
        for (int i = 0; i < 4; i++) {
            int id = tid + i * 256, row = id >> 3, c4 = id & 7;
            float vx[4] = {rx[i].x, rx[i].y, rx[i].z, rx[i].w};
            float vw[4] = {rw[i].x, rw[i].y, rw[i].z, rw[i].w};
            #pragma unroll
            for (int j = 0; j < 4; j++) {
                int kc = c4 * 4 + j;
                int phys = (kc & ~7) | ph8(kc & 7);
                sX[b * 5120 + row * 40 + phys] = rna_tf32(vx[j]);
                sW[b * 5120 + row * 40 + phys] = rna_tf32(vw[j]);
            }
        }
    };
    auto COMP = [&](int b) {
        const float* bx = sX + b * 5120;
        const float* bw = sW + b * 5120;
        #pragma unroll
        for (int kk = 0; kk < 4; kk++) {
            int ko = 2 * (kk * 4 + tg);
            unsigned a[2][4];
            #pragma unroll
            for (int mt = 0; mt < 2; mt++) {
                int r = wm * 32 + mt * 16 + g;
                float2 lo = *(const float2*)(bx + r * 40 + ko);
                float2 hi = *(const float2*)(bx + (r + 8) * 40 + ko);
                a[mt][0] = __float_as_uint(lo.x); a[mt][2] = __float_as_uint(lo.y);
                a[mt][1] = __float_as_uint(hi.x); a[mt][3] = __float_as_uint(hi.y);
            }
            #pragma unroll
            for (int nt = 0; nt < 8; nt++) {
                int n = wn * 64 + nt * 8 + g;
                float2 bb = *(const float2*)(bw + n * 40 + ko);
                unsigned b0 = __float_as_uint(bb.x), b1 = __float_as_uint(bb.y);
                #pragma unroll
                for (int mt = 0; mt < 2; mt++)
                    mma_tf32(c[mt][nt], a[mt][0], a[mt][1], a[mt][2], a[mt][3], b0, b1);
            }
        }
    };

    LDG(0); STS(0); __syncthreads();
    #pragma unroll 1
    for (int kb = 0; kb < 32; kb++) {
        if (kb < 31) LDG((kb + 1) * 32);
        COMP(kb & 1);
        if (kb < 31) STS((kb + 1) & 1);
        __syncthreads();
    }

    // Epilogue: bias + scatter. Q,K fp32 natural; V fp16 transposed [h][d][s].
    #pragma unroll
    for (int mt = 0; mt < 2; mt++) {
        int r0 = m0 + wm * 32 + mt * 16 + g;
        #pragma unroll
        for (int nt = 0; nt < 8; nt++) {
            int n = n0 + wn * 64 + nt * 8 + 2 * tg;
            float b0 = bias[n], b1 = bias[n + 1];
            int type = n >> 10, head = (n & 1023) >> 7, d = n & 127;
            float v0 = c[mt][nt][0] + b0, v1 = c[mt][nt][1] + b1;
            float v2 = c[mt][nt][2] + b0, v3 = c[mt][nt][3] + b1;
            if (type == 0) {
                float* dst = g_Q + ((size_t)head * S_LEN + r0) * HD + d;
                *(float2*)dst = make_float2(v0, v1);
                *(float2*)(dst + 8 * HD) = make_float2(v2, v3);
            } else if (type == 1) {
                float* dst = g_K + ((size_t)head * S_LEN + r0) * HD + d;
                *(float2*)dst = make_float2(v0, v1);
                *(float2*)(dst + 8 * HD) = make_float2(v2, v3);
            } else {
                __half* d0 = g_Vh + ((size_t)head * HD + d) * S_LEN;
                __half* d1 = d0 + S_LEN;
                d0[r0]     = __float2half_rn(v0); d1[r0]     = __float2half_rn(v1);
                d0[r0 + 8] = __float2half_rn(v2); d1[r0 + 8] = __float2half_rn(v3);
            }
        }
    }
}

// ---------------------------------------------------------------------------
// Kernel B: RoPE -> tf32, k pair-permuted Q (scale folded) and K.
// ---------------------------------------------------------------------------
__global__ __launch_bounds__(512) void rope_tf32(
    const float* __restrict__ cosp, const float* __restrict__ sinp)
{
    const int s = blockIdx.x, tid = threadIdx.x;
    const int head = tid >> 6, d = tid & 63;
    const float SCALE = 0.08838834764831845f;  // 128^-0.5

    float c1 = cosp[s * HD + d],      s1 = sinp[s * HD + d];
    float c2 = cosp[s * HD + d + 64], s2 = sinp[s * HD + d + 64];

    size_t base = ((size_t)head * S_LEN + s) * HD;
    int p1 = (d & ~7) | ph8(d & 7);
    int p2 = ((d + 64) & ~7) | ph8(d & 7);

    float q1 = g_Q[base + d], q2 = g_Q[base + d + 64];
    g_Qp[base + p1] = rna_tf32((q1 * c1 - q2 * s1) * SCALE);
    g_Qp[base + p2] = rna_tf32((q2 * c2 + q1 * s2) * SCALE);

    float k1 = g_K[base + d], k2 = g_K[base + d + 64];
    g_Kp[base + p1] = rna_tf32(k1 * c1 - k2 * s1);
    g_Kp[base + p2] = rna_tf32(k2 * c2 + k1 * s2);
}

// ---------------------------------------------------------------------------
// Kernel C: causal flash attention. BM=128, BN=64, 8 warps (warp = 16 rows).
// QK^T tf32 mma; P held in regs as fp16 A-fragments; PV fp16 mma.
// smem: sQ[128x136f] | sK 2x[64x136f] | sV 2x[128x72h]. Total 176128 B.
// ---------------------------------------------------------------------------
__global__ __launch_bounds__(256) void attn_tc(float* __restrict__ out)
{
    extern __shared__ float sm[];
    const int head = blockIdx.y;
    const int mb = 63 - (int)blockIdx.x;     // heavy tiles first
    const int q0 = mb * 128;
    const int tid = threadIdx.x, lane = tid & 31, w = tid >> 5;
    const int g = lane >> 2, tg = lane & 3;

    const float*  Qp = g_Qp + (size_t)head * S_LEN * HD;
    const float*  Kp = g_Kp + (size_t)head * S_LEN * HD;
    const __half* Vh = g_Vh + (size_t)head * HD * S_LEN;

    unsigned sb = (unsigned)__cvta_generic_to_shared(sm);

    // Prologue: Q (16 chunks/thr), K0 (8), V0 (4)
    #pragma unroll
    for (int i = 0; i < 16; i++) {
        int id = tid + i * 256, row = id >> 5, ch = id & 31;
        cpa16(sb + (unsigned)(row * 544 + ch * 16),
              Qp + (size_t)(q0 + row) * HD + ch * 4);
    }
    #pragma unroll
    for (int i = 0; i < 8; i++) {
        int id = tid + i * 256, row = id >> 5, ch = id & 31;
        cpa16(sb + 69632u + (unsigned)(row * 544 + ch * 16),
              Kp + (size_t)row * HD + ch * 4);
    }
    #pragma unroll
    for (int i = 0; i < 4; i++) {
        int id = tid + i * 256, row = id >> 3, ch = id & 7;
        cpa16(sb + 139264u + (unsigned)(row * 144 + ch * 16),
              Vh + (size_t)row * S_LEN + ch * 8);
    }
    CP_COMMIT;

    float m0r = -INFINITY, m1r = -INFINITY, l0 = 0.f, l1 = 0.f;
    float o[16][4];
    #pragma unroll
    for (int i = 0; i < 16; i++)
        #pragma unroll
        for (int j = 0; j < 4; j++) o[i][j] = 0.f;

    const int nblocks = 2 * (mb + 1);
    const int r0 = w * 16 + g;

    CP_WAIT0;
    __syncthreads();

    #pragma unroll 1
    for (int ib = 0; ib < nblocks; ib++) {
        // prefetch next K/V
        if (ib + 1 < nblocks) {
            int k0 = (ib + 1) * 64;
            unsigned bo = (unsigned)((ib + 1) & 1);
            #pragma unroll
            for (int i = 0; i < 8; i++) {
                int id = tid + i * 256, row = id >> 5, ch = id & 31;
                cpa16(sb + 69632u + bo * 34816u + (unsigned)(row * 544 + ch * 16),
                      Kp + (size_t)(k0 + row) * HD + ch * 4);
            }
            #pragma unroll
            for (int i = 0; i < 4; i++) {
                int id = tid + i * 256, row = id >> 3, ch = id & 7;
                cpa16(sb + 139264u + bo * 18432u + (unsigned)(row * 144 + ch * 16),
                      Vh + (size_t)row * S_LEN + k0 + ch * 8);
            }
            CP_COMMIT;
        }

        const float*  bK = sm + 17408 + (ib & 1) * 8704;
        const __half* bV = (const __half*)sm + 69632 + (ib & 1) * 9216;

        // ---- S = Q K^T (tf32)
        float c[8][4];
        #pragma unroll
        for (int i = 0; i < 8; i++)
            #pragma unroll
            for (int j = 0; j < 4; j++) c[i][j] = 0.f;

        #pragma unroll
        for (int kk = 0; kk < 16; kk++) {
            int ko = 2 * (kk * 4 + tg);
            float2 lo = *(const float2*)(sm + r0 * 136 + ko);
            float2 hi = *(const float2*)(sm + (r0 + 8) * 136 + ko);
            unsigned a0 = __float_as_uint(lo.x), a2 = __float_as_uint(lo.y);
            unsigned a1 = __float_as_uint(hi.x), a3 = __float_as_uint(hi.y);
            #pragma unroll
            for (int nt = 0; nt < 8; nt++) {
                float2 bb = *(const float2*)(bK + (nt * 8 + g) * 136 + ko);
                mma_tf32(c[nt], a0, a1, a2, a3,
                         __float_as_uint(bb.x), __float_as_uint(bb.y));
            }
        }

        // ---- causal mask (last two 64-blocks only)
        if (ib >= 2 * mb) {
            int k0 = ib * 64;
            int qr0 = q0 + r0, qr1 = qr0 + 8;
            #pragma unroll
            for (int nt = 0; nt < 8; nt++) {
                int col = k0 + nt * 8 + 2 * tg;
                if (col > qr0)     c[nt][0] = NEG;
                if (col + 1 > qr0) c[nt][1] = NEG;
                if (col > qr1)     c[nt][2] = NEG;
                if (col + 1 > qr1) c[nt][3] = NEG;
            }
        }

        // ---- online softmax
        float mx0 = NEG, mx1 = NEG;
        #pragma unroll
        for (int nt = 0; nt < 8; nt++) {
            mx0 = fmaxf(mx0, fmaxf(c[nt][0], c[nt][1]));
            mx1 = fmaxf(mx1, fmaxf(c[nt][2], c[nt][3]));
        }
        mx0 = fmaxf(mx0, __shfl_xor_sync(~0u, mx0, 1));
        mx0 = fmaxf(mx0, __shfl_xor_sync(~0u, mx0, 2));
        mx1 = fmaxf(mx1, __shfl_xor_sync(~0u, mx1, 1));
        mx1 = fmaxf(mx1, __shfl_xor_sync(~0u, mx1, 2));
        float mn0 = fmaxf(m0r, mx0), mn1 = fmaxf(m1r, mx1);
        float al0 = __expf(m0r - mn0), al1 = __expf(m1r - mn1);
        m0r = mn0; m1r = mn1;

        unsigned pa[8][2];
        float rs0 = 0.f, rs1 = 0.f;
        #pragma unroll
        for (int nt = 0; nt < 8; nt++) {
            float p0 = __expf(c[nt][0] - mn0), p1 = __expf(c[nt][1] - mn0);
            float p2 = __expf(c[nt][2] - mn1), p3 = __expf(c[nt][3] - mn1);
            rs0 += p0 + p1; rs1 += p2 + p3;
            __half2 h0 = __floats2half2_rn(p0, p1);
            __half2 h1 = __floats2half2_rn(p2, p3);
            pa[nt][0] = *(unsigned*)&h0; pa[nt][1] = *(unsigned*)&h1;
        }
        rs0 += __shfl_xor_sync(~0u, rs0, 1); rs0 += __shfl_xor_sync(~0u, rs0, 2);
        rs1 += __shfl_xor_sync(~0u, rs1, 1); rs1 += __shfl_xor_sync(~0u, rs1, 2);
        l0 = l0 * al0 + rs0; l1 = l1 * al1 + rs1;

        #pragma unroll
        for (int i = 0; i < 16; i++) {
            o[i][0] *= al0; o[i][1] *= al0;
            o[i][2] *= al1; o[i][3] *= al1;
        }

        // ---- O += P @ V (fp16)
        #pragma unroll
        for (int kc = 0; kc < 4; kc++) {
            unsigned a0 = pa[2*kc][0],   a1 = pa[2*kc][1];
            unsigned a2 = pa[2*kc+1][0], a3 = pa[2*kc+1][1];
            #pragma unroll
            for (int nt = 0; nt < 16; nt++) {
                const __half* vp = bV + (nt * 8 + g) * 72 + kc * 16 + 2 * tg;
                unsigned b0 = *(const unsigned*)vp;
                unsigned b1 = *(const unsigned*)(vp + 8);
                mma_f16(o[nt], a0, a1, a2, a3, b0, b1);
            }
        }

        if (ib + 1 < nblocks) { CP_WAIT0; }
        __syncthreads();
    }

    // ---- epilogue: normalize, write out[s][head][d]
    float inv0 = 1.f / l0, inv1 = 1.f / l1;
    size_t ro0 = (size_t)(q0 + r0) * (NHEAD * HD) + head * HD;
    size_t ro1 = ro0 + 8 * (NHEAD * HD);
    #pragma unroll
    for (int nt = 0; nt < 16; nt++) {
        int dcol = nt * 8 + 2 * tg;
        *(float2*)(out + ro0 + dcol) = make_float2(o[nt][0] * inv0, o[nt][1] * inv0);
        *(float2*)(out + ro1 + dcol) = make_float2(o[nt][2] * inv1, o[nt][3] * inv1);
    }
}

// ---------------------------------------------------------------------------
extern "C" void kernel_launch(void* const* d_in, const int* in_sizes, int n_in,
                              void* d_out, int out_size)
{
    const float* x  = (const float*)d_in[0];
    const float* fc = (const float*)d_in[1];
    const float* fs = (const float*)d_in[2];
    const float* w  = (const float*)d_in[3];
    const float* b  = (const float*)d_in[4];
    float* out = (float*)d_out;

    const int gemm_smem = 81920;
    cudaFuncSetAttribute(qkv_gemm_tf32,
        cudaFuncAttributeMaxDynamicSharedMemorySize, gemm_smem);
    qkv_gemm_tf32<<<dim3(24, 64), 256, gemm_smem>>>(x, w, b);

    rope_tf32<<<S_LEN, 512>>>(fc, fs);

    const int attn_smem = 176128;
    cudaFuncSetAttribute(attn_tc,
        cudaFuncAttributeMaxDynamicSharedMemorySize, attn_smem);
    attn_tc<<<dim3(64, NHEAD), 256, attn_smem>>>(out);
}